// round 15
// baseline (speedup 1.0000x reference)
#include <cuda_runtime.h>
#include <cuda_fp16.h>
#include <cstdint>
#include <math.h>

#define Hh 12
#define Dd 768
#define T1c 512
#define T2c 64
#define Bb 16
#define SPAD 68

static const float PROJ_SCALE = 0.3535533905932738f; // 64^-0.25
#define NEGBIG (-1e9f)

// ======================= PTX helpers (baseline ISA only) ====================
__device__ __forceinline__ uint32_t smem_to_u32(const void* p) {
    uint32_t a;
    asm("{ .reg .u64 t; cvta.to.shared.u64 t, %1; cvt.u32.u64 %0, t; }" : "=r"(a) : "l"(p));
    return a;
}
__device__ __forceinline__ void cp16(uint32_t saddr, const void* g) {
    asm volatile("cp.async.ca.shared.global [%0], [%1], 16;" :: "r"(saddr), "l"(g));
}
__device__ __forceinline__ void ldsm4(uint32_t* r, uint32_t addr) {
    asm volatile("ldmatrix.sync.aligned.m8n8.x4.shared.b16 {%0,%1,%2,%3}, [%4];"
        : "=r"(r[0]), "=r"(r[1]), "=r"(r[2]), "=r"(r[3]) : "r"(addr));
}
__device__ __forceinline__ void mma_f16(float* c, const uint32_t* a, const uint32_t* b) {
    asm volatile(
        "mma.sync.aligned.m16n8k16.row.col.f32.f16.f16.f32 "
        "{%0,%1,%2,%3}, {%4,%5,%6,%7}, {%8,%9}, {%0,%1,%2,%3};"
        : "+f"(c[0]), "+f"(c[1]), "+f"(c[2]), "+f"(c[3])
        : "r"(a[0]), "r"(a[1]), "r"(a[2]), "r"(a[3]), "r"(b[0]), "r"(b[1]));
}

// ======================= scratch (device globals) ===========================
__device__ float g_proj_f[6ull * Bb * T1c * Dd];   // [6][B][H][T1][64]
__device__ float g_proj_i[6ull * Bb * T2c * Dd];   // [6][B][H][T2][64]

__device__ __half g_fa[(size_t)Bb * T1c * Dd];
__device__ __half g_ia[(size_t)Bb * T2c * Dd];
// 14 weight matrices, fp16, K-major [z][N][K]: [0..5]=W_f [6..11]=W_i [12]=Wu_v [13]=Wu_l
__device__ __half g_wh[14ull * Dd * Dd];
__device__ __half g_av[(size_t)Bb * T1c * Dd];
__device__ __half g_al[(size_t)Bb * T2c * Dd];

// ======================= single merged conversion kernel ====================
// z in [0,13]: weight matrix z -> [z][N][K] fp16 (transposed, 24x24 xy tiles)
// z == 14:   feats -> fa (flat cast, grid-stride)
// z == 15:   inps  -> ia (flat cast, grid-stride)
__global__ __launch_bounds__(256) void conv_all(
    const float* __restrict__ feats, const float* __restrict__ inps,
    const float* __restrict__ W_f, const float* __restrict__ W_i,
    const float* __restrict__ Wu_v, const float* __restrict__ Wu_l,
    __half* __restrict__ fa, __half* __restrict__ ia, __half* __restrict__ bh)
{
    const int z = blockIdx.z;
    if (z >= 14) {
        const float* src = (z == 14) ? feats : inps;
        __half* dst = (z == 14) ? fa : ia;
        const int n = (z == 14) ? (Bb * T1c * Dd) : (Bb * T2c * Dd);
        const int stride = 24 * 24 * 256;
        for (int i = (blockIdx.y * 24 + blockIdx.x) * 256 + threadIdx.x; i < n; i += stride)
            dst[i] = __float2half_rn(src[i]);
        return;
    }
    __shared__ float t[32][33];
    const float* Wz;
    if (z < 6)       Wz = W_f  + (size_t)z * Dd * Dd;
    else if (z < 12) Wz = W_i  + (size_t)(z - 6) * Dd * Dd;
    else if (z == 12) Wz = Wu_v;
    else             Wz = Wu_l;
    const int k0 = blockIdx.y * 32, n0 = blockIdx.x * 32;
    const int tx = threadIdx.x & 31, ty = threadIdx.x >> 5; // 32 x 8
#pragma unroll
    for (int j = 0; j < 32; j += 8)
        t[ty + j][tx] = Wz[(size_t)(k0 + ty + j) * Dd + n0 + tx];
    __syncthreads();
#pragma unroll
    for (int j = 0; j < 32; j += 8) {
        float v = t[tx][ty + j];  // = W[k0+tx][n0+ty+j]
        size_t o = (size_t)z * Dd * Dd + (size_t)(n0 + ty + j) * Dd + k0 + tx;
        bh[o] = __float2half_rn(v);
    }
}

// ======================= mma.sync fp16 GEMM (unchanged from best) ===========
#define ROWB  80                  // 32 halfs + 8 pad = 80 bytes/row
#define TILE_A (128 * ROWB)       // 10240
#define TILE_Bb (256 * ROWB)      // 20480
#define STAGE_B (TILE_A + TILE_Bb) // 30720
#define GEMM_SMEM (2 * STAGE_B)   // 61440

__global__ __launch_bounds__(256, 1) void gemm_mma(
    const __half* __restrict__ Ah,
    const __half* __restrict__ Bh,
    const float* __restrict__ biasbase, float* __restrict__ Cbase,
    int M, int T, float scale, int mode)
{
    extern __shared__ __align__(16) char smem[];
    const uint32_t sb = smem_to_u32(smem);
    const int tid = threadIdx.x, lane = tid & 31, wid = tid >> 5;
    const int wm = wid & 1, wn = wid >> 1;          // warp tile 64m x 64n
    const int z = blockIdx.z;
    const int m0 = blockIdx.y * 128, n0 = blockIdx.x * 256;

    const __half* Asrc = Ah;
    const __half* Bsrc = Bh + (size_t)z * Dd * Dd;

    float acc[4][8][4];
#pragma unroll
    for (int a = 0; a < 4; a++)
#pragma unroll
        for (int b = 0; b < 8; b++)
#pragma unroll
            for (int c = 0; c < 4; c++) acc[a][b][c] = 0.0f;

#define LOAD_STAGE(kc, s) do {                                                \
    _Pragma("unroll")                                                         \
    for (int u_ = 0; u_ < 2; u_++) {                                          \
        const int idx_ = tid + u_ * 256;                                      \
        const int row_ = idx_ >> 2, cc_ = idx_ & 3;                           \
        cp16(sb + (s) * STAGE_B + row_ * ROWB + cc_ * 16,                     \
             Asrc + (size_t)(m0 + row_) * Dd + (kc) * 32 + cc_ * 8);          \
    }                                                                         \
    _Pragma("unroll")                                                         \
    for (int u_ = 0; u_ < 4; u_++) {                                          \
        const int idx_ = tid + u_ * 256;                                      \
        const int row_ = idx_ >> 2, cc_ = idx_ & 3;                           \
        cp16(sb + (s) * STAGE_B + TILE_A + row_ * ROWB + cc_ * 16,            \
             Bsrc + (size_t)(n0 + row_) * Dd + (kc) * 32 + cc_ * 8);          \
    }                                                                         \
    asm volatile("cp.async.commit_group;" ::: "memory");                      \
} while (0)

    LOAD_STAGE(0, 0);

    for (int i = 0; i < 24; i++) {
        const int s = i & 1;
        if (i + 1 < 24) {
            LOAD_STAGE(i + 1, s ^ 1);
            asm volatile("cp.async.wait_group 1;" ::: "memory");
        } else {
            asm volatile("cp.async.wait_group 0;" ::: "memory");
        }
        __syncthreads();

        const uint32_t st = sb + s * STAGE_B;
#pragma unroll
        for (int ks = 0; ks < 2; ks++) {
            const int kb = ks * 32;
            uint32_t b[8][2];
#pragma unroll
            for (int p = 0; p < 4; p++) {
                uint32_t r[4];
                uint32_t ab = st + TILE_A +
                              (wn * 64 + p * 16 + (lane & 15)) * ROWB +
                              ((lane >> 4) * 16) + kb;
                ldsm4(r, ab);
                b[p * 2][0] = r[0]; b[p * 2 + 1][0] = r[1];
                b[p * 2][1] = r[2]; b[p * 2 + 1][1] = r[3];
            }
            uint32_t a[4][4];
#pragma unroll
            for (int mt = 0; mt < 4; mt++) {
                const uint32_t ar = (wm * 64 + mt * 16 + (lane & 15)) * ROWB +
                                    ((lane >> 4) * 16) + kb;
                ldsm4(a[mt], st + ar);
            }
#pragma unroll
            for (int mt = 0; mt < 4; mt++)
#pragma unroll
                for (int nt = 0; nt < 8; nt++)
                    mma_f16(acc[mt][nt], a[mt], b[nt]);
        }
        __syncthreads();
    }

    const float* bias = biasbase + (size_t)z * Dd;
    float* C = Cbase + (size_t)z * M * Dd;
#pragma unroll
    for (int mt = 0; mt < 4; mt++)
#pragma unroll
        for (int nt = 0; nt < 8; nt++) {
            const int n = n0 + wn * 64 + nt * 8 + (lane & 3) * 2;
            const float2 bv = *(const float2*)&bias[n];
#pragma unroll
            for (int hf = 0; hf < 2; hf++) {
                const int m = m0 + wm * 64 + mt * 16 + (lane >> 2) + hf * 8;
                float2 v;
                v.x = scale * (acc[mt][nt][hf * 2 + 0] + bv.x);
                v.y = scale * (acc[mt][nt][hf * 2 + 1] + bv.y);
                if (mode == 0) {
                    const int b_ = m / T, t_ = m - b_ * T;
                    const int h = n >> 6, e = n & 63;
                    *(float2*)&C[((((size_t)(b_ * Hh + h)) * T + t_) << 6) + e] = v;
                } else {
                    *(float2*)&C[(size_t)m * Dd + n] = v;
                }
            }
        }
}

// ======================= flash attention (unchanged, now profiled) ==========
__global__ __launch_bounds__(256) void flash_kernel(
    const float* __restrict__ Q1,
    const float* __restrict__ Q2,
    const float* __restrict__ K1,
    const float* __restrict__ V1,
    const float* __restrict__ K2,
    const float* __restrict__ V2,
    const int* __restrict__ mask,
    __half* __restrict__ outh,
    int Tq)
{
    extern __shared__ __align__(16) float sm[];
    float* Qs   = sm;
    float* Ks   = Qs + 64 * SPAD;
    float* Vs   = Ks + 64 * SPAD;
    float* Ss   = Vs + 64 * 64;
    float* m_s  = Ss + 64 * SPAD;
    float* l_s  = m_s + 64;
    float* corr = l_s + 64;
    float* mflag = corr + 64;

    const int tid = threadIdx.x;
    const int tx = tid & 15;
    const int ty = tid >> 4;
    const int b = blockIdx.z, h = blockIdx.y, qt = blockIdx.x;

    const float* Q1p = Q1 + (((size_t)(b * Hh + h) * Tq) + qt * 64) * 64;
    const float* Q2p = Q2 + (((size_t)(b * Hh + h) * Tq) + qt * 64) * 64;
    const float* K1p = K1 + ((size_t)(b * Hh + h) * T1c) * 64;
    const float* V1p = V1 + ((size_t)(b * Hh + h) * T1c) * 64;
    const float* K2p = K2 + ((size_t)(b * Hh + h) * T2c) * 64;
    const float* V2p = V2 + ((size_t)(b * Hh + h) * T2c) * 64;

    for (int i = tid; i < 64 * 64; i += 256) {
        const int r = i >> 6, e = i & 63;
        Qs[e * SPAD + r] = Q1p[i];
    }
    for (int j = tid; j < T1c + T2c; j += 256)
        mflag[j] = (mask[b * (T1c + T2c) + j] != 0) ? 1.0f : 0.0f;
    if (tid < 64) { m_s[tid] = -1e30f; l_s[tid] = 0.0f; }

    float acc[4][4];
#pragma unroll
    for (int i = 0; i < 4; i++)
#pragma unroll
        for (int j = 0; j < 4; j++) acc[i][j] = 0.0f;

    for (int kt = 0; kt < 9; kt++) {
        const float* Kt;
        const float* Vt;
        int koff;
        if (kt < 8) { Kt = K1p + kt * 64 * 64; Vt = V1p + kt * 64 * 64; koff = kt * 64; }
        else        { Kt = K2p;               Vt = V2p;               koff = T1c; }

        __syncthreads();
        if (kt == 8) {
            for (int i = tid; i < 64 * 64; i += 256) {
                const int r = i >> 6, e = i & 63;
                Qs[e * SPAD + r] = Q2p[i];
            }
        }
        for (int i = tid; i < 64 * 64; i += 256) {
            const int j = i >> 6, e = i & 63;
            Ks[e * SPAD + j] = Kt[i];
        }
        for (int i = tid * 4; i < 64 * 64; i += 256 * 4)
            *(float4*)&Vs[i] = *(const float4*)&Vt[i];
        __syncthreads();

        float s[4][4];
#pragma unroll
        for (int i = 0; i < 4; i++)
#pragma unroll
            for (int j = 0; j < 4; j++) s[i][j] = 0.0f;
#pragma unroll 8
        for (int e = 0; e < 64; e++) {
            const float4 q  = *(const float4*)&Qs[e * SPAD + tx * 4];
            const float4 kv = *(const float4*)&Ks[e * SPAD + ty * 4];
            const float qa[4] = {q.x, q.y, q.z, q.w};
            const float ka[4] = {kv.x, kv.y, kv.z, kv.w};
#pragma unroll
            for (int i = 0; i < 4; i++)
#pragma unroll
                for (int j = 0; j < 4; j++)
                    s[i][j] += qa[i] * ka[j];
        }
#pragma unroll
        for (int jj = 0; jj < 4; jj++) {
            const float mf = mflag[koff + ty * 4 + jj];
            float4 v;
            v.x = (mf != 0.0f) ? NEGBIG : s[0][jj];
            v.y = (mf != 0.0f) ? NEGBIG : s[1][jj];
            v.z = (mf != 0.0f) ? NEGBIG : s[2][jj];
            v.w = (mf != 0.0f) ? NEGBIG : s[3][jj];
            *(float4*)&Ss[(ty * 4 + jj) * SPAD + tx * 4] = v;
        }
        __syncthreads();

        if (tid < 64) {
            const float mold = m_s[tid];
            float mx = mold;
            for (int j = 0; j < 64; j++) mx = fmaxf(mx, Ss[j * SPAD + tid]);
            const float c = __expf(mold - mx);
            float sum = 0.0f;
            for (int j = 0; j < 64; j++) {
                const float p = __expf(Ss[j * SPAD + tid] - mx);
                Ss[j * SPAD + tid] = p;
                sum += p;
            }
            l_s[tid] = l_s[tid] * c + sum;
            m_s[tid] = mx;
            corr[tid] = c;
        }
        __syncthreads();

        const float c0 = corr[tx * 4 + 0];
        const float c1 = corr[tx * 4 + 1];
        const float c2 = corr[tx * 4 + 2];
        const float c3 = corr[tx * 4 + 3];
#pragma unroll
        for (int j = 0; j < 4; j++) {
            acc[0][j] *= c0; acc[1][j] *= c1; acc[2][j] *= c2; acc[3][j] *= c3;
        }
#pragma unroll 8
        for (int kk = 0; kk < 64; kk++) {
            const float4 p = *(const float4*)&Ss[kk * SPAD + tx * 4];
            const float4 v = *(const float4*)&Vs[kk * 64 + ty * 4];
            const float pa[4] = {p.x, p.y, p.z, p.w};
            const float va[4] = {v.x, v.y, v.z, v.w};
#pragma unroll
            for (int i = 0; i < 4; i++)
#pragma unroll
                for (int j = 0; j < 4; j++)
                    acc[i][j] += pa[i] * va[j];
        }
    }

    __syncthreads();
#pragma unroll
    for (int ii = 0; ii < 4; ii++) {
        const int r = tx * 4 + ii;
        const float inv = 1.0f / l_s[r];
        const int row = qt * 64 + r;
        const size_t base = ((size_t)b * Tq + row) * Dd + h * 64 + ty * 4;
        __align__(8) __half hv[4];
#pragma unroll
        for (int j = 0; j < 4; j++)
            hv[j] = __float2half_rn(acc[ii][j] * inv);
        *(uint2*)&outh[base] = *(uint2*)hv;
    }
}

// ======================= launch =============================================
extern "C" void kernel_launch(void* const* d_in, const int* in_sizes, int n_in,
                              void* d_out, int out_size)
{
    const float* feats = (const float*)d_in[0];
    const float* inps  = (const float*)d_in[1];
    const int*   mask  = (const int*)d_in[2];
    const float* W_f  = (const float*)d_in[3];
    const float* b_f  = (const float*)d_in[4];
    const float* W_i  = (const float*)d_in[5];
    const float* b_i  = (const float*)d_in[6];
    const float* Wu_v = (const float*)d_in[7];
    const float* bu_v = (const float*)d_in[8];
    const float* Wu_l = (const float*)d_in[9];
    const float* bu_l = (const float*)d_in[10];
    float* out = (float*)d_out;

    float *pf, *pi;
    cudaGetSymbolAddress((void**)&pf, g_proj_f);
    cudaGetSymbolAddress((void**)&pi, g_proj_i);
    __half *fa, *ia, *wh, *av, *al;
    cudaGetSymbolAddress((void**)&fa, g_fa);
    cudaGetSymbolAddress((void**)&ia, g_ia);
    cudaGetSymbolAddress((void**)&wh, g_wh);
    cudaGetSymbolAddress((void**)&av, g_av);
    cudaGetSymbolAddress((void**)&al, g_al);

    const size_t SF = (size_t)Bb * T1c * Dd;  // 6291456
    const size_t SI = (size_t)Bb * T2c * Dd;  // 786432
    const size_t WSZ = (size_t)Dd * Dd;       // 589824

    cudaFuncSetAttribute(gemm_mma, cudaFuncAttributeMaxDynamicSharedMemorySize, GEMM_SMEM);
    const int fsm = (3 * 64 * SPAD + 64 * 64 + 3 * 64 + (T1c + T2c)) * (int)sizeof(float);
    cudaFuncSetAttribute(flash_kernel, cudaFuncAttributeMaxDynamicSharedMemorySize, fsm);

    // 1: single merged conversion launch (weights z=0..13, feats z=14, inps z=15)
    conv_all<<<dim3(24, 24, 16), 256>>>(feats, inps, W_f, W_i, Wu_v, Wu_l, fa, ia, wh);

    // 2, 3: projection GEMMs
    gemm_mma<<<dim3(3, 64, 6), 256, GEMM_SMEM>>>(fa, wh, b_f, pf,
                                                 Bb * T1c, T1c, PROJ_SCALE, 0);
    gemm_mma<<<dim3(3, 8, 6), 256, GEMM_SMEM>>>(ia, wh + 6 * WSZ, b_i, pi,
                                                Bb * T2c, T2c, PROJ_SCALE, 0);

    // 4: big flash (PROFILED this round — in-graph duration finally visible)
    flash_kernel<<<dim3(8, Hh, Bb), 256, fsm>>>(
        pf + 1 * SF, pf + 3 * SF, pf + 0 * SF, pf + 2 * SF,
        pi + 0 * SI, pi + 1 * SI, mask, av, T1c);
    flash_kernel<<<dim3(1, Hh, Bb), 256, fsm>>>(
        pi + 2 * SI, pi + 3 * SI, pf + 4 * SF, pf + 5 * SF,
        pi + 4 * SI, pi + 5 * SI, mask, al, T2c);

    // output projections
    gemm_mma<<<dim3(3, 64, 1), 256, GEMM_SMEM>>>(av, wh + 12 * WSZ,
                                                 bu_v, out, Bb * T1c, T1c, 1.0f, 1);
    gemm_mma<<<dim3(3, 8, 1), 256, GEMM_SMEM>>>(al, wh + 13 * WSZ,
                                                bu_l, out + SF, Bb * T2c, T2c, 1.0f, 1);
}

// round 16
// speedup vs baseline: 1.4478x; 1.4478x over previous
#include <cuda_runtime.h>
#include <cuda_fp16.h>
#include <cstdint>
#include <math.h>

#define Hh 12
#define Dd 768
#define T1c 512
#define T2c 64
#define Bb 16

static const float PROJ_SCALE = 0.3535533905932738f; // 64^-0.25
#define NEGBIG (-1e9f)

// ======================= PTX helpers (baseline ISA only) ====================
__device__ __forceinline__ uint32_t smem_to_u32(const void* p) {
    uint32_t a;
    asm("{ .reg .u64 t; cvta.to.shared.u64 t, %1; cvt.u32.u64 %0, t; }" : "=r"(a) : "l"(p));
    return a;
}
__device__ __forceinline__ void cp16(uint32_t saddr, const void* g) {
    asm volatile("cp.async.ca.shared.global [%0], [%1], 16;" :: "r"(saddr), "l"(g));
}
__device__ __forceinline__ void ldsm4(uint32_t* r, uint32_t addr) {
    asm volatile("ldmatrix.sync.aligned.m8n8.x4.shared.b16 {%0,%1,%2,%3}, [%4];"
        : "=r"(r[0]), "=r"(r[1]), "=r"(r[2]), "=r"(r[3]) : "r"(addr));
}
__device__ __forceinline__ void mma_f16(float* c, const uint32_t* a, const uint32_t* b) {
    asm volatile(
        "mma.sync.aligned.m16n8k16.row.col.f32.f16.f16.f32 "
        "{%0,%1,%2,%3}, {%4,%5,%6,%7}, {%8,%9}, {%0,%1,%2,%3};"
        : "+f"(c[0]), "+f"(c[1]), "+f"(c[2]), "+f"(c[3])
        : "r"(a[0]), "r"(a[1]), "r"(a[2]), "r"(a[3]), "r"(b[0]), "r"(b[1]));
}

// ======================= scratch (device globals) ===========================
__device__ __half g_proj_f[6ull * Bb * T1c * Dd];   // [6][B][H][T1][64] fp16
__device__ __half g_proj_i[6ull * Bb * T2c * Dd];   // [6][B][H][T2][64] fp16

__device__ __half g_fa[(size_t)Bb * T1c * Dd];
__device__ __half g_ia[(size_t)Bb * T2c * Dd];
__device__ __half g_wh[14ull * Dd * Dd];  // [0..5]=W_f [6..11]=W_i [12]=Wu_v [13]=Wu_l
__device__ __half g_av[(size_t)Bb * T1c * Dd];
__device__ __half g_al[(size_t)Bb * T2c * Dd];

// ======================= merged conversion kernel ===========================
__global__ __launch_bounds__(256) void conv_all(
    const float* __restrict__ feats, const float* __restrict__ inps,
    const float* __restrict__ W_f, const float* __restrict__ W_i,
    const float* __restrict__ Wu_v, const float* __restrict__ Wu_l,
    __half* __restrict__ fa, __half* __restrict__ ia, __half* __restrict__ bh)
{
    const int z = blockIdx.z;
    if (z >= 14) {
        const float* src = (z == 14) ? feats : inps;
        __half* dst = (z == 14) ? fa : ia;
        const int n = (z == 14) ? (Bb * T1c * Dd) : (Bb * T2c * Dd);
        const int stride = 24 * 24 * 256;
        for (int i = (blockIdx.y * 24 + blockIdx.x) * 256 + threadIdx.x; i < n; i += stride)
            dst[i] = __float2half_rn(src[i]);
        return;
    }
    __shared__ float t[32][33];
    const float* Wz;
    if (z < 6)       Wz = W_f  + (size_t)z * Dd * Dd;
    else if (z < 12) Wz = W_i  + (size_t)(z - 6) * Dd * Dd;
    else if (z == 12) Wz = Wu_v;
    else             Wz = Wu_l;
    const int k0 = blockIdx.y * 32, n0 = blockIdx.x * 32;
    const int tx = threadIdx.x & 31, ty = threadIdx.x >> 5;
#pragma unroll
    for (int j = 0; j < 32; j += 8)
        t[ty + j][tx] = Wz[(size_t)(k0 + ty + j) * Dd + n0 + tx];
    __syncthreads();
#pragma unroll
    for (int j = 0; j < 32; j += 8) {
        float v = t[tx][ty + j];
        size_t o = (size_t)z * Dd * Dd + (size_t)(n0 + ty + j) * Dd + k0 + tx;
        bh[o] = __float2half_rn(v);
    }
}

// ======================= mma.sync fp16 GEMM =================================
// mode 0: scatter epilogue -> fp16 [B][H][T][64] (half2 stores)
// mode 1: plain epilogue -> fp32 [m][768]
#define ROWB  80
#define TILE_A (128 * ROWB)
#define TILE_Bb (256 * ROWB)
#define STAGE_B (TILE_A + TILE_Bb)
#define GEMM_SMEM (2 * STAGE_B)

__global__ __launch_bounds__(256, 1) void gemm_mma(
    const __half* __restrict__ Ah,
    const __half* __restrict__ Bh,
    const float* __restrict__ biasbase, void* __restrict__ Cbase,
    int M, int T, float scale, int mode)
{
    extern __shared__ __align__(16) char smem[];
    const uint32_t sb = smem_to_u32(smem);
    const int tid = threadIdx.x, lane = tid & 31, wid = tid >> 5;
    const int wm = wid & 1, wn = wid >> 1;
    const int z = blockIdx.z;
    const int m0 = blockIdx.y * 128, n0 = blockIdx.x * 256;

    const __half* Asrc = Ah;
    const __half* Bsrc = Bh + (size_t)z * Dd * Dd;

    float acc[4][8][4];
#pragma unroll
    for (int a = 0; a < 4; a++)
#pragma unroll
        for (int b = 0; b < 8; b++)
#pragma unroll
            for (int c = 0; c < 4; c++) acc[a][b][c] = 0.0f;

#define LOAD_STAGE(kc, s) do {                                                \
    _Pragma("unroll")                                                         \
    for (int u_ = 0; u_ < 2; u_++) {                                          \
        const int idx_ = tid + u_ * 256;                                      \
        const int row_ = idx_ >> 2, cc_ = idx_ & 3;                           \
        cp16(sb + (s) * STAGE_B + row_ * ROWB + cc_ * 16,                     \
             Asrc + (size_t)(m0 + row_) * Dd + (kc) * 32 + cc_ * 8);          \
    }                                                                         \
    _Pragma("unroll")                                                         \
    for (int u_ = 0; u_ < 4; u_++) {                                          \
        const int idx_ = tid + u_ * 256;                                      \
        const int row_ = idx_ >> 2, cc_ = idx_ & 3;                           \
        cp16(sb + (s) * STAGE_B + TILE_A + row_ * ROWB + cc_ * 16,            \
             Bsrc + (size_t)(n0 + row_) * Dd + (kc) * 32 + cc_ * 8);          \
    }                                                                         \
    asm volatile("cp.async.commit_group;" ::: "memory");                      \
} while (0)

    LOAD_STAGE(0, 0);

    for (int i = 0; i < 24; i++) {
        const int s = i & 1;
        if (i + 1 < 24) {
            LOAD_STAGE(i + 1, s ^ 1);
            asm volatile("cp.async.wait_group 1;" ::: "memory");
        } else {
            asm volatile("cp.async.wait_group 0;" ::: "memory");
        }
        __syncthreads();

        const uint32_t st = sb + s * STAGE_B;
#pragma unroll
        for (int ks = 0; ks < 2; ks++) {
            const int kb = ks * 32;
            uint32_t b[8][2];
#pragma unroll
            for (int p = 0; p < 4; p++) {
                uint32_t r[4];
                uint32_t ab = st + TILE_A +
                              (wn * 64 + p * 16 + (lane & 15)) * ROWB +
                              ((lane >> 4) * 16) + kb;
                ldsm4(r, ab);
                b[p * 2][0] = r[0]; b[p * 2 + 1][0] = r[1];
                b[p * 2][1] = r[2]; b[p * 2 + 1][1] = r[3];
            }
            uint32_t a[4][4];
#pragma unroll
            for (int mt = 0; mt < 4; mt++) {
                const uint32_t ar = (wm * 64 + mt * 16 + (lane & 15)) * ROWB +
                                    ((lane >> 4) * 16) + kb;
                ldsm4(a[mt], st + ar);
            }
#pragma unroll
            for (int mt = 0; mt < 4; mt++)
#pragma unroll
                for (int nt = 0; nt < 8; nt++)
                    mma_f16(acc[mt][nt], a[mt], b[nt]);
        }
        __syncthreads();
    }

    const float* bias = biasbase + (size_t)z * Dd;
#pragma unroll
    for (int mt = 0; mt < 4; mt++)
#pragma unroll
        for (int nt = 0; nt < 8; nt++) {
            const int n = n0 + wn * 64 + nt * 8 + (lane & 3) * 2;
            const float2 bv = *(const float2*)&bias[n];
#pragma unroll
            for (int hf = 0; hf < 2; hf++) {
                const int m = m0 + wm * 64 + mt * 16 + (lane >> 2) + hf * 8;
                float vx = scale * (acc[mt][nt][hf * 2 + 0] + bv.x);
                float vy = scale * (acc[mt][nt][hf * 2 + 1] + bv.y);
                if (mode == 0) {
                    __half* C = (__half*)Cbase + (size_t)z * M * Dd;
                    const int b_ = m / T, t_ = m - b_ * T;
                    const int h = n >> 6, e = n & 63;
                    *(__half2*)&C[((((size_t)(b_ * Hh + h)) * T + t_) << 6) + e] =
                        __floats2half2_rn(vx, vy);
                } else {
                    float* C = (float*)Cbase + (size_t)z * M * Dd;
                    float2 v; v.x = vx; v.y = vy;
                    *(float2*)&C[(size_t)m * Dd + n] = v;
                }
            }
        }
}

// ======================= flash attention (fp16 tensor cores) ================
// Block: 256 thr (8 warps). Warp = (wq=wid&3 -> 16 q-rows) x (we=wid>>2 -> 32 keys/e-dims).
// S = Q K^T and O += P V use the SAME validated ldsm mappings as gemm_mma
// (A row-major non-trans; B as [n][k] non-trans). V transposed explicitly into smem.
#define FP 72                      // fp16 tile pitch in halfs (144B = 9*16B)
#define SP 65                      // score pitch in floats
#define FL_SMEM (4 * 64 * FP * 2 + 64 * SP * 4 + 3 * 64 * 4 + 576 * 4)

__global__ __launch_bounds__(256) void flash_mma(
    const __half* __restrict__ Q1, const __half* __restrict__ Q2,
    const __half* __restrict__ K1, const __half* __restrict__ V1,
    const __half* __restrict__ K2, const __half* __restrict__ V2,
    const int* __restrict__ mask, __half* __restrict__ outh, int Tq)
{
    extern __shared__ __align__(16) char smraw[];
    __half* Qs = (__half*)smraw;            // [64][FP]
    __half* Ks = Qs + 64 * FP;
    __half* Vt = Ks + 64 * FP;              // transposed: [e][key]
    __half* Ps = Vt + 64 * FP;
    float* Sf  = (float*)(Ps + 64 * FP);    // [64][SP]
    float* m_s = Sf + 64 * SP;
    float* l_s = m_s + 64;
    float* corr = l_s + 64;
    float* mflag = corr + 64;               // [576]

    const uint32_t sb = smem_to_u32(smraw);
    const uint32_t uQs = sb;
    const uint32_t uKs = uQs + 64 * FP * 2;
    const uint32_t uVt = uKs + 64 * FP * 2;
    const uint32_t uPs = uVt + 64 * FP * 2;

    const int tid = threadIdx.x, lane = tid & 31, wid = tid >> 5;
    const int wq = wid & 3, we = wid >> 2;
    const int m0 = wq * 16, n0 = we * 32;
    const int b = blockIdx.z, h = blockIdx.y, qt = blockIdx.x;

    const __half* Q1p = Q1 + (((size_t)(b * Hh + h) * Tq) + qt * 64) * 64;
    const __half* Q2p = Q2 + (((size_t)(b * Hh + h) * Tq) + qt * 64) * 64;
    const __half* K1p = K1 + ((size_t)(b * Hh + h) * T1c) * 64;
    const __half* V1p = V1 + ((size_t)(b * Hh + h) * T1c) * 64;
    const __half* K2p = K2 + ((size_t)(b * Hh + h) * T2c) * 64;
    const __half* V2p = V2 + ((size_t)(b * Hh + h) * T2c) * 64;

#pragma unroll
    for (int u = 0; u < 2; u++) {
        const int idx = tid + u * 256, row = idx >> 3, c8 = idx & 7;
        *(uint4*)&Qs[row * FP + c8 * 8] = *(const uint4*)&Q1p[row * 64 + c8 * 8];
    }
    for (int j = tid; j < T1c + T2c; j += 256)
        mflag[j] = (mask[b * (T1c + T2c) + j] != 0) ? 1.0f : 0.0f;
    if (tid < 64) { m_s[tid] = -1e30f; l_s[tid] = 0.0f; }

    float acc_o[4][4];
#pragma unroll
    for (int i = 0; i < 4; i++)
#pragma unroll
        for (int j = 0; j < 4; j++) acc_o[i][j] = 0.0f;

    for (int kt = 0; kt < 9; kt++) {
        const __half* Kt;
        const __half* Vp;
        int koff;
        if (kt < 8) { Kt = K1p + kt * 64 * 64; Vp = V1p + kt * 64 * 64; koff = kt * 64; }
        else        { Kt = K2p;                Vp = V2p;                koff = T1c; }

        __syncthreads();
        if (kt == 8) {
#pragma unroll
            for (int u = 0; u < 2; u++) {
                const int idx = tid + u * 256, row = idx >> 3, c8 = idx & 7;
                *(uint4*)&Qs[row * FP + c8 * 8] = *(const uint4*)&Q2p[row * 64 + c8 * 8];
            }
        }
#pragma unroll
        for (int u = 0; u < 2; u++) {
            const int idx = tid + u * 256, row = idx >> 3, c8 = idx & 7;
            *(uint4*)&Ks[row * FP + c8 * 8] = *(const uint4*)&Kt[row * 64 + c8 * 8];
        }
        // V transpose: [k][e] -> Vt[e][k]
#pragma unroll
        for (int u = 0; u < 2; u++) {
            const int idx = tid + u * 256, k = idx >> 3, e0 = (idx & 7) * 8;
            uint4 v = *(const uint4*)&Vp[k * 64 + e0];
            const __half* vp = (const __half*)&v;
#pragma unroll
            for (int j = 0; j < 8; j++) Vt[(e0 + j) * FP + k] = vp[j];
        }
        __syncthreads();

        // S = Q K^T (m16 x n32 per warp)
        float s[4][4];
#pragma unroll
        for (int i = 0; i < 4; i++)
#pragma unroll
            for (int j = 0; j < 4; j++) s[i][j] = 0.0f;
#pragma unroll
        for (int ks = 0; ks < 4; ks++) {
            uint32_t a[4];
            ldsm4(a, uQs + (m0 + (lane & 15)) * (FP * 2) + ((lane >> 4) * 16) + ks * 32);
            uint32_t bf[4][2];
#pragma unroll
            for (int p = 0; p < 2; p++) {
                uint32_t r[4];
                ldsm4(r, uKs + (n0 + p * 16 + (lane & 15)) * (FP * 2) +
                          ((lane >> 4) * 16) + ks * 32);
                bf[p * 2][0] = r[0]; bf[p * 2 + 1][0] = r[1];
                bf[p * 2][1] = r[2]; bf[p * 2 + 1][1] = r[3];
            }
#pragma unroll
            for (int nt = 0; nt < 4; nt++) mma_f16(s[nt], a, bf[nt]);
        }
        // masked store to Sf
        const int rw = m0 + (lane >> 2);
#pragma unroll
        for (int nt = 0; nt < 4; nt++) {
            const int c = n0 + nt * 8 + (lane & 3) * 2;
            const bool mf0 = mflag[koff + c] != 0.0f;
            const bool mf1 = mflag[koff + c + 1] != 0.0f;
            Sf[rw * SP + c]           = mf0 ? NEGBIG : s[nt][0];
            Sf[rw * SP + c + 1]       = mf1 ? NEGBIG : s[nt][1];
            Sf[(rw + 8) * SP + c]     = mf0 ? NEGBIG : s[nt][2];
            Sf[(rw + 8) * SP + c + 1] = mf1 ? NEGBIG : s[nt][3];
        }
        __syncthreads();

        // online softmax, one thread per row; write P in fp16
        if (tid < 64) {
            const float mold = m_s[tid];
            float mx = mold;
            for (int j = 0; j < 64; j++) mx = fmaxf(mx, Sf[tid * SP + j]);
            const float c = __expf(mold - mx);
            float sum = 0.0f;
            for (int j = 0; j < 64; j++) {
                const float p = __expf(Sf[tid * SP + j] - mx);
                Ps[tid * FP + j] = __float2half_rn(p);
                sum += p;
            }
            l_s[tid] = l_s[tid] * c + sum;
            m_s[tid] = mx;
            corr[tid] = c;
        }
        __syncthreads();

        // rescale + O += P V
        const float clo = corr[m0 + (lane >> 2)];
        const float chi = corr[m0 + (lane >> 2) + 8];
#pragma unroll
        for (int nt = 0; nt < 4; nt++) {
            acc_o[nt][0] *= clo; acc_o[nt][1] *= clo;
            acc_o[nt][2] *= chi; acc_o[nt][3] *= chi;
        }
#pragma unroll
        for (int ks = 0; ks < 4; ks++) {
            uint32_t a[4];
            ldsm4(a, uPs + (m0 + (lane & 15)) * (FP * 2) + ((lane >> 4) * 16) + ks * 32);
            uint32_t bf[4][2];
#pragma unroll
            for (int p = 0; p < 2; p++) {
                uint32_t r[4];
                ldsm4(r, uVt + (n0 + p * 16 + (lane & 15)) * (FP * 2) +
                          ((lane >> 4) * 16) + ks * 32);
                bf[p * 2][0] = r[0]; bf[p * 2 + 1][0] = r[1];
                bf[p * 2][1] = r[2]; bf[p * 2 + 1][1] = r[3];
            }
#pragma unroll
            for (int nt = 0; nt < 4; nt++) mma_f16(acc_o[nt], a, bf[nt]);
        }
    }

    // write O (fp16, half2 stores)
    const float ilo = 1.0f / l_s[m0 + (lane >> 2)];
    const float ihi = 1.0f / l_s[m0 + (lane >> 2) + 8];
    const int qlo = qt * 64 + m0 + (lane >> 2);
#pragma unroll
    for (int nt = 0; nt < 4; nt++) {
        const int c = h * 64 + n0 + nt * 8 + (lane & 3) * 2;
        *(__half2*)&outh[((size_t)b * Tq + qlo) * Dd + c] =
            __floats2half2_rn(acc_o[nt][0] * ilo, acc_o[nt][1] * ilo);
        *(__half2*)&outh[((size_t)b * Tq + qlo + 8) * Dd + c] =
            __floats2half2_rn(acc_o[nt][2] * ihi, acc_o[nt][3] * ihi);
    }
}

// ======================= launch =============================================
extern "C" void kernel_launch(void* const* d_in, const int* in_sizes, int n_in,
                              void* d_out, int out_size)
{
    const float* feats = (const float*)d_in[0];
    const float* inps  = (const float*)d_in[1];
    const int*   mask  = (const int*)d_in[2];
    const float* W_f  = (const float*)d_in[3];
    const float* b_f  = (const float*)d_in[4];
    const float* W_i  = (const float*)d_in[5];
    const float* b_i  = (const float*)d_in[6];
    const float* Wu_v = (const float*)d_in[7];
    const float* bu_v = (const float*)d_in[8];
    const float* Wu_l = (const float*)d_in[9];
    const float* bu_l = (const float*)d_in[10];
    float* out = (float*)d_out;

    __half *pf, *pi, *fa, *ia, *wh, *av, *al;
    cudaGetSymbolAddress((void**)&pf, g_proj_f);
    cudaGetSymbolAddress((void**)&pi, g_proj_i);
    cudaGetSymbolAddress((void**)&fa, g_fa);
    cudaGetSymbolAddress((void**)&ia, g_ia);
    cudaGetSymbolAddress((void**)&wh, g_wh);
    cudaGetSymbolAddress((void**)&av, g_av);
    cudaGetSymbolAddress((void**)&al, g_al);

    const size_t SF = (size_t)Bb * T1c * Dd;
    const size_t SI = (size_t)Bb * T2c * Dd;
    const size_t WSZ = (size_t)Dd * Dd;

    cudaFuncSetAttribute(gemm_mma, cudaFuncAttributeMaxDynamicSharedMemorySize, GEMM_SMEM);
    cudaFuncSetAttribute(flash_mma, cudaFuncAttributeMaxDynamicSharedMemorySize, FL_SMEM);

    // 1: conversions
    conv_all<<<dim3(24, 24, 16), 256>>>(feats, inps, W_f, W_i, Wu_v, Wu_l, fa, ia, wh);

    // 2, 3: projection GEMMs (scatter fp16)
    gemm_mma<<<dim3(3, 64, 6), 256, GEMM_SMEM>>>(fa, wh, b_f, pf,
                                                 Bb * T1c, T1c, PROJ_SCALE, 0);
    gemm_mma<<<dim3(3, 8, 6), 256, GEMM_SMEM>>>(ia, wh + 6 * WSZ, b_i, pi,
                                                Bb * T2c, T2c, PROJ_SCALE, 0);

    // 4: big flash (profiled slot)
    flash_mma<<<dim3(8, Hh, Bb), 256, FL_SMEM>>>(
        pf + 1 * SF, pf + 3 * SF, pf + 0 * SF, pf + 2 * SF,
        pi + 0 * SI, pi + 1 * SI, mask, av, T1c);
    flash_mma<<<dim3(1, Hh, Bb), 256, FL_SMEM>>>(
        pi + 2 * SI, pi + 3 * SI, pf + 4 * SF, pf + 5 * SF,
        pi + 4 * SI, pi + 5 * SI, mask, al, T2c);

    // output projections (fp32 out)
    gemm_mma<<<dim3(3, 64, 1), 256, GEMM_SMEM>>>(av, wh + 12 * WSZ,
                                                 bu_v, out, Bb * T1c, T1c, 1.0f, 1);
    gemm_mma<<<dim3(3, 8, 1), 256, GEMM_SMEM>>>(al, wh + 13 * WSZ,
                                                bu_l, out + SF, Bb * T2c, T2c, 1.0f, 1);
}

// round 17
// speedup vs baseline: 1.8846x; 1.3017x over previous
#include <cuda_runtime.h>
#include <cuda_fp16.h>
#include <cstdint>
#include <math.h>

#define Hh 12
#define Dd 768
#define T1c 512
#define T2c 64
#define Bb 16

static const float PROJ_SCALE = 0.3535533905932738f; // 64^-0.25
#define NEGBIG (-1e9f)

// ======================= PTX helpers (baseline ISA only) ====================
__device__ __forceinline__ uint32_t smem_to_u32(const void* p) {
    uint32_t a;
    asm("{ .reg .u64 t; cvta.to.shared.u64 t, %1; cvt.u32.u64 %0, t; }" : "=r"(a) : "l"(p));
    return a;
}
__device__ __forceinline__ void cp16(uint32_t saddr, const void* g) {
    asm volatile("cp.async.ca.shared.global [%0], [%1], 16;" :: "r"(saddr), "l"(g));
}
__device__ __forceinline__ void ldsm4(uint32_t* r, uint32_t addr) {
    asm volatile("ldmatrix.sync.aligned.m8n8.x4.shared.b16 {%0,%1,%2,%3}, [%4];"
        : "=r"(r[0]), "=r"(r[1]), "=r"(r[2]), "=r"(r[3]) : "r"(addr));
}
__device__ __forceinline__ void ldsm4t(uint32_t* r, uint32_t addr) {
    asm volatile("ldmatrix.sync.aligned.m8n8.x4.trans.shared.b16 {%0,%1,%2,%3}, [%4];"
        : "=r"(r[0]), "=r"(r[1]), "=r"(r[2]), "=r"(r[3]) : "r"(addr));
}
__device__ __forceinline__ void mma_f16(float* c, const uint32_t* a, const uint32_t* b) {
    asm volatile(
        "mma.sync.aligned.m16n8k16.row.col.f32.f16.f16.f32 "
        "{%0,%1,%2,%3}, {%4,%5,%6,%7}, {%8,%9}, {%0,%1,%2,%3};"
        : "+f"(c[0]), "+f"(c[1]), "+f"(c[2]), "+f"(c[3])
        : "r"(a[0]), "r"(a[1]), "r"(a[2]), "r"(a[3]), "r"(b[0]), "r"(b[1]));
}

// ======================= scratch (device globals) ===========================
__device__ __half g_proj_f[6ull * Bb * T1c * Dd];   // [6][B][H][T1][64] fp16
__device__ __half g_proj_i[6ull * Bb * T2c * Dd];   // [6][B][H][T2][64] fp16

__device__ __half g_fa[(size_t)Bb * T1c * Dd];
__device__ __half g_ia[(size_t)Bb * T2c * Dd];
__device__ __half g_wh[14ull * Dd * Dd];  // [0..5]=W_f [6..11]=W_i [12]=Wu_v [13]=Wu_l
__device__ __half g_av[(size_t)Bb * T1c * Dd];
__device__ __half g_al[(size_t)Bb * T2c * Dd];

// ======================= merged conversion kernel ===========================
__global__ __launch_bounds__(256) void conv_all(
    const float* __restrict__ feats, const float* __restrict__ inps,
    const float* __restrict__ W_f, const float* __restrict__ W_i,
    const float* __restrict__ Wu_v, const float* __restrict__ Wu_l,
    __half* __restrict__ fa, __half* __restrict__ ia, __half* __restrict__ bh)
{
    const int z = blockIdx.z;
    if (z >= 14) {
        const float* src = (z == 14) ? feats : inps;
        __half* dst = (z == 14) ? fa : ia;
        const int n = (z == 14) ? (Bb * T1c * Dd) : (Bb * T2c * Dd);
        const int stride = 24 * 24 * 256;
        for (int i = (blockIdx.y * 24 + blockIdx.x) * 256 + threadIdx.x; i < n; i += stride)
            dst[i] = __float2half_rn(src[i]);
        return;
    }
    __shared__ float t[32][33];
    const float* Wz;
    if (z < 6)       Wz = W_f  + (size_t)z * Dd * Dd;
    else if (z < 12) Wz = W_i  + (size_t)(z - 6) * Dd * Dd;
    else if (z == 12) Wz = Wu_v;
    else             Wz = Wu_l;
    const int k0 = blockIdx.y * 32, n0 = blockIdx.x * 32;
    const int tx = threadIdx.x & 31, ty = threadIdx.x >> 5;
#pragma unroll
    for (int j = 0; j < 32; j += 8)
        t[ty + j][tx] = Wz[(size_t)(k0 + ty + j) * Dd + n0 + tx];
    __syncthreads();
#pragma unroll
    for (int j = 0; j < 32; j += 8) {
        float v = t[tx][ty + j];
        size_t o = (size_t)z * Dd * Dd + (size_t)(n0 + ty + j) * Dd + k0 + tx;
        bh[o] = __float2half_rn(v);
    }
}

// ======================= mma.sync fp16 GEMM (unchanged) =====================
#define ROWB  80
#define TILE_A (128 * ROWB)
#define TILE_Bb (256 * ROWB)
#define STAGE_B (TILE_A + TILE_Bb)
#define GEMM_SMEM (2 * STAGE_B)

__global__ __launch_bounds__(256, 1) void gemm_mma(
    const __half* __restrict__ Ah,
    const __half* __restrict__ Bh,
    const float* __restrict__ biasbase, void* __restrict__ Cbase,
    int M, int T, float scale, int mode)
{
    extern __shared__ __align__(16) char smem[];
    const uint32_t sb = smem_to_u32(smem);
    const int tid = threadIdx.x, lane = tid & 31, wid = tid >> 5;
    const int wm = wid & 1, wn = wid >> 1;
    const int z = blockIdx.z;
    const int m0 = blockIdx.y * 128, n0 = blockIdx.x * 256;

    const __half* Asrc = Ah;
    const __half* Bsrc = Bh + (size_t)z * Dd * Dd;

    float acc[4][8][4];
#pragma unroll
    for (int a = 0; a < 4; a++)
#pragma unroll
        for (int b = 0; b < 8; b++)
#pragma unroll
            for (int c = 0; c < 4; c++) acc[a][b][c] = 0.0f;

#define LOAD_STAGE(kc, s) do {                                                \
    _Pragma("unroll")                                                         \
    for (int u_ = 0; u_ < 2; u_++) {                                          \
        const int idx_ = tid + u_ * 256;                                      \
        const int row_ = idx_ >> 2, cc_ = idx_ & 3;                           \
        cp16(sb + (s) * STAGE_B + row_ * ROWB + cc_ * 16,                     \
             Asrc + (size_t)(m0 + row_) * Dd + (kc) * 32 + cc_ * 8);          \
    }                                                                         \
    _Pragma("unroll")                                                         \
    for (int u_ = 0; u_ < 4; u_++) {                                          \
        const int idx_ = tid + u_ * 256;                                      \
        const int row_ = idx_ >> 2, cc_ = idx_ & 3;                           \
        cp16(sb + (s) * STAGE_B + TILE_A + row_ * ROWB + cc_ * 16,            \
             Bsrc + (size_t)(n0 + row_) * Dd + (kc) * 32 + cc_ * 8);          \
    }                                                                         \
    asm volatile("cp.async.commit_group;" ::: "memory");                      \
} while (0)

    LOAD_STAGE(0, 0);

    for (int i = 0; i < 24; i++) {
        const int s = i & 1;
        if (i + 1 < 24) {
            LOAD_STAGE(i + 1, s ^ 1);
            asm volatile("cp.async.wait_group 1;" ::: "memory");
        } else {
            asm volatile("cp.async.wait_group 0;" ::: "memory");
        }
        __syncthreads();

        const uint32_t st = sb + s * STAGE_B;
#pragma unroll
        for (int ks = 0; ks < 2; ks++) {
            const int kb = ks * 32;
            uint32_t b[8][2];
#pragma unroll
            for (int p = 0; p < 4; p++) {
                uint32_t r[4];
                uint32_t ab = st + TILE_A +
                              (wn * 64 + p * 16 + (lane & 15)) * ROWB +
                              ((lane >> 4) * 16) + kb;
                ldsm4(r, ab);
                b[p * 2][0] = r[0]; b[p * 2 + 1][0] = r[1];
                b[p * 2][1] = r[2]; b[p * 2 + 1][1] = r[3];
            }
            uint32_t a[4][4];
#pragma unroll
            for (int mt = 0; mt < 4; mt++) {
                const uint32_t ar = (wm * 64 + mt * 16 + (lane & 15)) * ROWB +
                                    ((lane >> 4) * 16) + kb;
                ldsm4(a[mt], st + ar);
            }
#pragma unroll
            for (int mt = 0; mt < 4; mt++)
#pragma unroll
                for (int nt = 0; nt < 8; nt++)
                    mma_f16(acc[mt][nt], a[mt], b[nt]);
        }
        __syncthreads();
    }

    const float* bias = biasbase + (size_t)z * Dd;
#pragma unroll
    for (int mt = 0; mt < 4; mt++)
#pragma unroll
        for (int nt = 0; nt < 8; nt++) {
            const int n = n0 + wn * 64 + nt * 8 + (lane & 3) * 2;
            const float2 bv = *(const float2*)&bias[n];
#pragma unroll
            for (int hf = 0; hf < 2; hf++) {
                const int m = m0 + wm * 64 + mt * 16 + (lane >> 2) + hf * 8;
                float vx = scale * (acc[mt][nt][hf * 2 + 0] + bv.x);
                float vy = scale * (acc[mt][nt][hf * 2 + 1] + bv.y);
                if (mode == 0) {
                    __half* C = (__half*)Cbase + (size_t)z * M * Dd;
                    const int b_ = m / T, t_ = m - b_ * T;
                    const int h = n >> 6, e = n & 63;
                    *(__half2*)&C[((((size_t)(b_ * Hh + h)) * T + t_) << 6) + e] =
                        __floats2half2_rn(vx, vy);
                } else {
                    float* C = (float*)Cbase + (size_t)z * M * Dd;
                    float2 v; v.x = vx; v.y = vy;
                    *(float2*)&C[(size_t)m * Dd + n] = v;
                }
            }
        }
}

// ======================= flash attention (fp16 tensor cores) ================
// 8 warps: (wq=wid&3 -> 16 q-rows) x (we=wid>>2 -> 32 keys / 32 e-dims).
// QK: validated non-trans A/B paths. PV: V kept [key][e]; B via ldsm4t
// (trans tiles: bf[p*2]={r0,r1}, bf[p*2+1]={r2,r3}). Softmax: 4 thr/row.
#define FP 72                      // fp16 tile pitch in halfs (144B)
#define SP 68                      // score pitch in floats (16B-aligned rows)
#define FL_SMEM (4 * 64 * FP * 2 + 64 * SP * 4 + 3 * 64 * 4 + 576 * 4)

__global__ __launch_bounds__(256) void flash_mma(
    const __half* __restrict__ Q1, const __half* __restrict__ Q2,
    const __half* __restrict__ K1, const __half* __restrict__ V1,
    const __half* __restrict__ K2, const __half* __restrict__ V2,
    const int* __restrict__ mask, __half* __restrict__ outh, int Tq)
{
    extern __shared__ __align__(16) char smraw[];
    __half* Qs = (__half*)smraw;            // [64][FP]
    __half* Ks = Qs + 64 * FP;
    __half* Vs = Ks + 64 * FP;              // [key][e] as loaded
    __half* Ps = Vs + 64 * FP;
    float* Sf  = (float*)(Ps + 64 * FP);    // [64][SP]
    float* m_s = Sf + 64 * SP;
    float* l_s = m_s + 64;
    float* corr = l_s + 64;
    float* mflag = corr + 64;               // [576]

    const uint32_t sb = smem_to_u32(smraw);
    const uint32_t uQs = sb;
    const uint32_t uKs = uQs + 64 * FP * 2;
    const uint32_t uVs = uKs + 64 * FP * 2;
    const uint32_t uPs = uVs + 64 * FP * 2;

    const int tid = threadIdx.x, lane = tid & 31, wid = tid >> 5;
    const int wq = wid & 3, we = wid >> 2;
    const int m0 = wq * 16, n0 = we * 32;
    const int b = blockIdx.z, h = blockIdx.y, qt = blockIdx.x;

    const __half* Q1p = Q1 + (((size_t)(b * Hh + h) * Tq) + qt * 64) * 64;
    const __half* Q2p = Q2 + (((size_t)(b * Hh + h) * Tq) + qt * 64) * 64;
    const __half* K1p = K1 + ((size_t)(b * Hh + h) * T1c) * 64;
    const __half* V1p = V1 + ((size_t)(b * Hh + h) * T1c) * 64;
    const __half* K2p = K2 + ((size_t)(b * Hh + h) * T2c) * 64;
    const __half* V2p = V2 + ((size_t)(b * Hh + h) * T2c) * 64;

#pragma unroll
    for (int u = 0; u < 2; u++) {
        const int idx = tid + u * 256, row = idx >> 3, c8 = idx & 7;
        *(uint4*)&Qs[row * FP + c8 * 8] = *(const uint4*)&Q1p[row * 64 + c8 * 8];
    }
    for (int j = tid; j < T1c + T2c; j += 256)
        mflag[j] = (mask[b * (T1c + T2c) + j] != 0) ? 1.0f : 0.0f;
    if (tid < 64) { m_s[tid] = -1e30f; l_s[tid] = 0.0f; }

    float acc_o[4][4];
#pragma unroll
    for (int i = 0; i < 4; i++)
#pragma unroll
        for (int j = 0; j < 4; j++) acc_o[i][j] = 0.0f;

    for (int kt = 0; kt < 9; kt++) {
        const __half* Kt;
        const __half* Vp;
        int koff;
        if (kt < 8) { Kt = K1p + kt * 64 * 64; Vp = V1p + kt * 64 * 64; koff = kt * 64; }
        else        { Kt = K2p;                Vp = V2p;                koff = T1c; }

        __syncthreads();
        if (kt == 8) {
#pragma unroll
            for (int u = 0; u < 2; u++) {
                const int idx = tid + u * 256, row = idx >> 3, c8 = idx & 7;
                *(uint4*)&Qs[row * FP + c8 * 8] = *(const uint4*)&Q2p[row * 64 + c8 * 8];
            }
        }
#pragma unroll
        for (int u = 0; u < 2; u++) {
            const int idx = tid + u * 256, row = idx >> 3, c8 = idx & 7;
            *(uint4*)&Ks[row * FP + c8 * 8] = *(const uint4*)&Kt[row * 64 + c8 * 8];
            *(uint4*)&Vs[row * FP + c8 * 8] = *(const uint4*)&Vp[row * 64 + c8 * 8];
        }
        __syncthreads();

        // S = Q K^T (m16 x n32 per warp)
        float s[4][4];
#pragma unroll
        for (int i = 0; i < 4; i++)
#pragma unroll
            for (int j = 0; j < 4; j++) s[i][j] = 0.0f;
#pragma unroll
        for (int ks = 0; ks < 4; ks++) {
            uint32_t a[4];
            ldsm4(a, uQs + (m0 + (lane & 15)) * (FP * 2) + ((lane >> 4) * 16) + ks * 32);
            uint32_t bf[4][2];
#pragma unroll
            for (int p = 0; p < 2; p++) {
                uint32_t r[4];
                ldsm4(r, uKs + (n0 + p * 16 + (lane & 15)) * (FP * 2) +
                          ((lane >> 4) * 16) + ks * 32);
                bf[p * 2][0] = r[0]; bf[p * 2 + 1][0] = r[1];
                bf[p * 2][1] = r[2]; bf[p * 2 + 1][1] = r[3];
            }
#pragma unroll
            for (int nt = 0; nt < 4; nt++) mma_f16(s[nt], a, bf[nt]);
        }
        // masked store to Sf
        const int rw = m0 + (lane >> 2);
#pragma unroll
        for (int nt = 0; nt < 4; nt++) {
            const int c = n0 + nt * 8 + (lane & 3) * 2;
            const bool mf0 = mflag[koff + c] != 0.0f;
            const bool mf1 = mflag[koff + c + 1] != 0.0f;
            Sf[rw * SP + c]           = mf0 ? NEGBIG : s[nt][0];
            Sf[rw * SP + c + 1]       = mf1 ? NEGBIG : s[nt][1];
            Sf[(rw + 8) * SP + c]     = mf0 ? NEGBIG : s[nt][2];
            Sf[(rw + 8) * SP + c + 1] = mf1 ? NEGBIG : s[nt][3];
        }
        __syncthreads();

        // parallel online softmax: 4 threads per row (all 256 threads)
        {
            const int row = tid >> 2, sub = tid & 3;
            const float mold = m_s[row];
            float mx = mold;
            float4 v[4];
#pragma unroll
            for (int j = 0; j < 4; j++) {
                v[j] = *(float4*)&Sf[row * SP + sub * 16 + j * 4];
                mx = fmaxf(mx, fmaxf(fmaxf(v[j].x, v[j].y), fmaxf(v[j].z, v[j].w)));
            }
            mx = fmaxf(mx, __shfl_xor_sync(0xffffffffu, mx, 1));
            mx = fmaxf(mx, __shfl_xor_sync(0xffffffffu, mx, 2));
            float sum = 0.0f;
#pragma unroll
            for (int j = 0; j < 4; j++) {
                const float p0 = __expf(v[j].x - mx), p1 = __expf(v[j].y - mx);
                const float p2 = __expf(v[j].z - mx), p3 = __expf(v[j].w - mx);
                sum += (p0 + p1) + (p2 + p3);
                *(__half2*)&Ps[row * FP + sub * 16 + j * 4]     = __floats2half2_rn(p0, p1);
                *(__half2*)&Ps[row * FP + sub * 16 + j * 4 + 2] = __floats2half2_rn(p2, p3);
            }
            sum += __shfl_xor_sync(0xffffffffu, sum, 1);
            sum += __shfl_xor_sync(0xffffffffu, sum, 2);
            if (sub == 0) {
                const float c = __expf(mold - mx);
                l_s[row] = l_s[row] * c + sum;
                m_s[row] = mx;
                corr[row] = c;
            }
        }
        __syncthreads();

        // rescale + O += P V  (V via ldsm trans: B = V^T[e][key])
        const float clo = corr[m0 + (lane >> 2)];
        const float chi = corr[m0 + (lane >> 2) + 8];
#pragma unroll
        for (int nt = 0; nt < 4; nt++) {
            acc_o[nt][0] *= clo; acc_o[nt][1] *= clo;
            acc_o[nt][2] *= chi; acc_o[nt][3] *= chi;
        }
#pragma unroll
        for (int ks = 0; ks < 4; ks++) {
            uint32_t a[4];
            ldsm4(a, uPs + (m0 + (lane & 15)) * (FP * 2) + ((lane >> 4) * 16) + ks * 32);
            uint32_t bf[4][2];
#pragma unroll
            for (int p = 0; p < 2; p++) {
                uint32_t r[4];
                // rows = 16 keys of this ks step; cols = e segment (n0 + p*16)
                ldsm4t(r, uVs + (ks * 16 + (lane & 15)) * (FP * 2) +
                           ((lane >> 4) * 16) + (n0 + p * 16) * 2);
                bf[p * 2][0] = r[0];     bf[p * 2][1] = r[1];      // e 0-7:  k0-7, k8-15
                bf[p * 2 + 1][0] = r[2]; bf[p * 2 + 1][1] = r[3];  // e 8-15: k0-7, k8-15
            }
#pragma unroll
            for (int nt = 0; nt < 4; nt++) mma_f16(acc_o[nt], a, bf[nt]);
        }
    }

    // write O (fp16, half2 stores)
    const float ilo = 1.0f / l_s[m0 + (lane >> 2)];
    const float ihi = 1.0f / l_s[m0 + (lane >> 2) + 8];
    const int qlo = qt * 64 + m0 + (lane >> 2);
#pragma unroll
    for (int nt = 0; nt < 4; nt++) {
        const int c = h * 64 + n0 + nt * 8 + (lane & 3) * 2;
        *(__half2*)&outh[((size_t)b * Tq + qlo) * Dd + c] =
            __floats2half2_rn(acc_o[nt][0] * ilo, acc_o[nt][1] * ilo);
        *(__half2*)&outh[((size_t)b * Tq + qlo + 8) * Dd + c] =
            __floats2half2_rn(acc_o[nt][2] * ihi, acc_o[nt][3] * ihi);
    }
}

// ======================= launch =============================================
extern "C" void kernel_launch(void* const* d_in, const int* in_sizes, int n_in,
                              void* d_out, int out_size)
{
    const float* feats = (const float*)d_in[0];
    const float* inps  = (const float*)d_in[1];
    const int*   mask  = (const int*)d_in[2];
    const float* W_f  = (const float*)d_in[3];
    const float* b_f  = (const float*)d_in[4];
    const float* W_i  = (const float*)d_in[5];
    const float* b_i  = (const float*)d_in[6];
    const float* Wu_v = (const float*)d_in[7];
    const float* bu_v = (const float*)d_in[8];
    const float* Wu_l = (const float*)d_in[9];
    const float* bu_l = (const float*)d_in[10];
    float* out = (float*)d_out;

    __half *pf, *pi, *fa, *ia, *wh, *av, *al;
    cudaGetSymbolAddress((void**)&pf, g_proj_f);
    cudaGetSymbolAddress((void**)&pi, g_proj_i);
    cudaGetSymbolAddress((void**)&fa, g_fa);
    cudaGetSymbolAddress((void**)&ia, g_ia);
    cudaGetSymbolAddress((void**)&wh, g_wh);
    cudaGetSymbolAddress((void**)&av, g_av);
    cudaGetSymbolAddress((void**)&al, g_al);

    const size_t SF = (size_t)Bb * T1c * Dd;
    const size_t SI = (size_t)Bb * T2c * Dd;
    const size_t WSZ = (size_t)Dd * Dd;

    cudaFuncSetAttribute(gemm_mma, cudaFuncAttributeMaxDynamicSharedMemorySize, GEMM_SMEM);
    cudaFuncSetAttribute(flash_mma, cudaFuncAttributeMaxDynamicSharedMemorySize, FL_SMEM);

    // 1: conversions
    conv_all<<<dim3(24, 24, 16), 256>>>(feats, inps, W_f, W_i, Wu_v, Wu_l, fa, ia, wh);

    // 2, 3: projection GEMMs (scatter fp16)
    gemm_mma<<<dim3(3, 64, 6), 256, GEMM_SMEM>>>(fa, wh, b_f, pf,
                                                 Bb * T1c, T1c, PROJ_SCALE, 0);
    gemm_mma<<<dim3(3, 8, 6), 256, GEMM_SMEM>>>(ia, wh + 6 * WSZ, b_i, pi,
                                                Bb * T2c, T2c, PROJ_SCALE, 0);

    // 4: big flash (profiled slot)
    flash_mma<<<dim3(8, Hh, Bb), 256, FL_SMEM>>>(
        pf + 1 * SF, pf + 3 * SF, pf + 0 * SF, pf + 2 * SF,
        pi + 0 * SI, pi + 1 * SI, mask, av, T1c);
    flash_mma<<<dim3(1, Hh, Bb), 256, FL_SMEM>>>(
        pi + 2 * SI, pi + 3 * SI, pf + 4 * SF, pf + 5 * SF,
        pi + 4 * SI, pi + 5 * SI, mask, al, T2c);

    // output projections (fp32 out)
    gemm_mma<<<dim3(3, 64, 1), 256, GEMM_SMEM>>>(av, wh + 12 * WSZ,
                                                 bu_v, out, Bb * T1c, T1c, 1.0f, 1);
    gemm_mma<<<dim3(3, 8, 1), 256, GEMM_SMEM>>>(al, wh + 13 * WSZ,
                                                bu_l, out + SF, Bb * T2c, T2c, 1.0f, 1);
}